// round 16
// baseline (speedup 1.0000x reference)
#include <cuda_runtime.h>
#include <math.h>

#define BB 8
#define CC 128
#define LL 4096
#define DM 32
#define DI 64
#define NCH 64
#define QQ 64

// ---------------- scratch ----------------
__device__ float g_o1[BB*LL*CC];
__device__ float g_s[BB*LL*DM];
__device__ float g_z[2*BB*LL*DI];
__device__ float g_dA[2*BB*LL];
__device__ float g_xs[2*BB*LL*64];
__device__ float g_Bm[2*BB*LL*64];
__device__ float g_Cm[2*BB*LL*64];
__device__ float g_dtx[2*BB*LL*64];
__device__ float g_S[2*BB*NCH*64*64];
__device__ float g_E[2*BB*NCH];
__device__ float g_hinit[2*BB*NCH*64*64];
__device__ float g_yn[2*BB*LL*64];
__device__ float g_o3[BB*LL*CC];
__device__ float g_part[512*256];
__device__ float g_w4eff[CC*CC];
__device__ float g_b4eff[CC];

__device__ __forceinline__ float siluf(float v){ return __fdividef(v, 1.f+__expf(-v)); }
__device__ __forceinline__ float sigf(float v){ return __fdividef(1.f, 1.f+__expf(-v)); }

// ---- packed f32x2 helpers ----
typedef unsigned long long u64t;
__device__ __forceinline__ u64t pack2(float x){
    u64t r; asm("mov.b64 %0, {%1, %1};" : "=l"(r) : "f"(x)); return r;
}
__device__ __forceinline__ u64t mul2(u64t a, u64t b){
    u64t r; asm("mul.rn.f32x2 %0, %1, %2;" : "=l"(r) : "l"(a), "l"(b)); return r;
}
__device__ __forceinline__ u64t fma2(u64t a, u64t b, u64t c){
    u64t r; asm("fma.rn.f32x2 %0, %1, %2, %3;" : "=l"(r) : "l"(a), "l"(b), "l"(c)); return r;
}
__device__ __forceinline__ u64t add2(u64t a, u64t b){
    u64t r; asm("add.rn.f32x2 %0, %1, %2;" : "=l"(r) : "l"(a), "l"(b)); return r;
}
__device__ __forceinline__ float2 unpack2(u64t v){
    float2 f; asm("mov.b64 {%0, %1}, %2;" : "=f"(f.x), "=f"(f.y) : "l"(v)); return f;
}
__device__ __forceinline__ int swz2(int idx){
    int c = idx & 15;
    return (idx & ~15) | ((c&7)<<1) | (c>>3);
}

// ---------------- kernel 0: dummy (shifts ncu -s window onto k_inproj_f) ----------------
__global__ void k_dummy(){}

// ---------------- kernel 1: lin1 (f32x2) ----------------
__global__ __launch_bounds__(256) void k_lin1(const float* __restrict__ x,
                                              const float* __restrict__ W,
                                              const float* __restrict__ bias){
    __shared__ float As[128][36];
    __shared__ float Bs[32][132];
    int b = blockIdx.y, l0 = blockIdx.x*128;
    int tid = threadIdx.x;
    int ty = tid>>4, tx = tid&15;
    u64t acc2[8][4];
    #pragma unroll
    for (int j=0;j<8;j++)
        #pragma unroll
        for (int q=0;q<4;q++) acc2[j][q]=0ull;
    const float* Xb = x + (size_t)b*CC*LL;
    for (int k0=0;k0<128;k0+=32){
        #pragma unroll
        for (int p=0;p<16;p++){ int idx = tid + p*256; int kk = idx>>7; int ll = idx&127;
            As[ll][kk] = Xb[(size_t)(k0+kk)*LL + l0+ll]; }
        #pragma unroll
        for (int p=0;p<16;p++){ int idx = tid + p*256; int kk = idx>>7; int oo = idx&127;
            Bs[kk][oo] = W[(size_t)(k0+kk)*CC + oo]; }
        __syncthreads();
        #pragma unroll
        for (int k=0;k<32;k+=4){
            float4 a4[8];
            #pragma unroll
            for (int j=0;j<8;j++) a4[j] = *(const float4*)(&As[ty*8+j][k]);
            #pragma unroll
            for (int kk=0;kk<4;kk++){
                ulonglong2 b0 = *(const ulonglong2*)(&Bs[k+kk][tx*8]);
                ulonglong2 b1 = *(const ulonglong2*)(&Bs[k+kk][tx*8+4]);
                #pragma unroll
                for (int j=0;j<8;j++){
                    float a = (kk==0)? a4[j].x : (kk==1)? a4[j].y : (kk==2)? a4[j].z : a4[j].w;
                    u64t a2 = pack2(a);
                    acc2[j][0]=fma2(a2,b0.x,acc2[j][0]);
                    acc2[j][1]=fma2(a2,b0.y,acc2[j][1]);
                    acc2[j][2]=fma2(a2,b1.x,acc2[j][2]);
                    acc2[j][3]=fma2(a2,b1.y,acc2[j][3]);
                }
            }
        }
        __syncthreads();
    }
    ulonglong2 bb0 = *(const ulonglong2*)&bias[tx*8];
    ulonglong2 bb1 = *(const ulonglong2*)&bias[tx*8+4];
    #pragma unroll
    for (int j=0;j<8;j++){
        int l = l0 + ty*8 + j;
        float* op = g_o1 + ((size_t)b*LL + l)*CC + tx*8;
        ulonglong2 r0, r1;
        r0.x = add2(acc2[j][0], bb0.x); r0.y = add2(acc2[j][1], bb0.y);
        r1.x = add2(acc2[j][2], bb1.x); r1.y = add2(acc2[j][3], bb1.y);
        *(ulonglong2*)op = r0; *(ulonglong2*)(op+4) = r1;
    }
}

// ---------------- kernel 2: fused depthwise 3x3 + silu + fc_in GEMM (slab halo, 66KB) ----
#define DWFC_SMEM_FLOATS (6800 + 8448 + 1188 + 128)
__global__ __launch_bounds__(256) void k_dwfc(const float* __restrict__ w3,
                                              const float* __restrict__ db,
                                              const float* __restrict__ Wf){
    extern __shared__ float sm1[];
    float* halo = sm1;                 // [100][68] current 64-ch slab
    float* o2t  = halo + 6800;         // [64][132]
    float* w3t  = o2t + 8448;          // 9*132 tap-major
    float* dbs  = w3t + 1188;          // 128
    int w0 = blockIdx.x*8, h0 = blockIdx.y*8, b = blockIdx.z;
    int tid = threadIdx.x;
    // independent prologue
    for (int i=tid;i<1152;i+=256){ int tap=i>>7, ch=i&127; w3t[tap*132+ch]=w3[ch*9+tap]; }
    if (tid<128) dbs[tid]=db[tid];
    cudaGridDependencySynchronize();   // wait for lin1's g_o1
    int px = tid>>2, c2 = tid&3;
    int py = px>>3, pxx = px&7;
    #pragma unroll
    for (int slab=0; slab<2; slab++){
        int ch0 = slab*64;
        __syncthreads();     // protect halo from previous slab's readers
        for (int i=tid;i<1600;i+=256){
            int pos = i>>4, k4 = i&15;
            int hy = pos/10, wx = pos - hy*10;
            int hh = h0-1+hy, ww = w0-1+wx;
            float4 v = make_float4(0.f,0.f,0.f,0.f);
            if (hh>=0 && hh<64 && ww>=0 && ww<64)
                v = *(const float4*)(g_o1 + ((size_t)(b*4096 + hh*64+ww))*128 + ch0 + k4*4);
            *(float4*)(halo + pos*68 + k4*4) = v;
        }
        __syncthreads();
        #pragma unroll
        for (int g=0;g<4;g++){
            int chl = g*16 + c2*4;
            int ch = ch0 + chl;
            float4 acc = *(const float4*)&dbs[ch];
            #pragma unroll
            for (int dy=0;dy<3;dy++)
                #pragma unroll
                for (int dx=0;dx<3;dx++){
                    float4 wv = *(const float4*)&w3t[(dy*3+dx)*132 + ch];
                    float4 hv = *(const float4*)&halo[((py+dy)*10 + pxx+dx)*68 + chl];
                    acc.x += wv.x*hv.x; acc.y += wv.y*hv.y;
                    acc.z += wv.z*hv.z; acc.w += wv.w*hv.w;
                }
            float4 r; r.x=siluf(acc.x); r.y=siluf(acc.y); r.z=siluf(acc.z); r.w=siluf(acc.w);
            *(float4*)&o2t[px*132 + ch] = r;
        }
    }
    __syncthreads();
    int d0 = (tid&3)*8;
    float acc[8];
    #pragma unroll
    for (int j=0;j<8;j++) acc[j]=0.f;
    #pragma unroll 4
    for (int k=0;k<128;k++){
        float v = o2t[px*132 + k];
        float4 wA = __ldg((const float4*)(Wf + k*32 + d0));
        float4 wB = __ldg((const float4*)(Wf + k*32 + d0 + 4));
        acc[0]+=v*wA.x; acc[1]+=v*wA.y; acc[2]+=v*wA.z; acc[3]+=v*wA.w;
        acc[4]+=v*wB.x; acc[5]+=v*wB.y; acc[6]+=v*wB.z; acc[7]+=v*wB.w;
    }
    int l = (h0+py)*64 + (w0+pxx);
    float* so = g_s + ((size_t)b*4096 + l)*32 + d0;
    *(float4*)so     = make_float4(acc[0],acc[1],acc[2],acc[3]);
    *(float4*)(so+4) = make_float4(acc[4],acc[5],acc[6],acc[7]);
}

// ---------------- kernel 3: fused in-projection + conv1d ----------------
#define IROWS 32
#define IROWSH 35
#define INP_SMEM_FLOATS (8224 + IROWSH*36 + IROWSH*192 + 36 + 768 + 192)
__global__ __launch_bounds__(256) void k_inproj_f(const float* __restrict__ Win,
                                                  const float* __restrict__ dtb,
                                                  const float* __restrict__ Alog,
                                                  const float* __restrict__ cw,
                                                  const float* __restrict__ cb){
    extern __shared__ float sm2[];
    float* ws   = sm2;
    float* sr   = ws + 8224;
    float* xbcs = sr + IROWSH*36;
    float* dts  = xbcs + IROWSH*192;
    float* cwt  = dts + 36;
    float* cbs  = cwt + 768;
    int dir = blockIdx.z, b = blockIdx.y, l0 = blockIdx.x*IROWS;
    int tid = threadIdx.x;
    const float* Wp = Win + dir*8224;
    for (int i=tid;i<8224;i+=256) ws[i] = Wp[i];
    for (int i=tid;i<768;i+=256){ int tap=i/192, ch=i-tap*192; cwt[i] = cw[dir*768 + ch*4 + tap]; }
    if (tid<192) cbs[tid] = cb[dir*192+tid];
    cudaGridDependencySynchronize();   // wait for dwfc's g_s
    for (int i=tid;i<IROWSH*8;i+=256){
        int row = i>>3, k4 = i&7;
        int l = l0-3+row;
        float4 v = make_float4(0.f,0.f,0.f,0.f);
        if (l >= 0){
            int ls = dir ? (LL-1-l) : l;
            v = *(const float4*)(g_s + ((size_t)b*LL + ls)*32 + k4*4);
        }
        *(float4*)(sr + row*36 + k4*4) = v;
    }
    __syncthreads();
    int c = tid & 127, r = tid >> 7;
    float wc0[32], wc1[32];
    #pragma unroll
    for (int k=0;k<32;k++){ wc0[k]=ws[k*257+c]; wc1[k]=ws[k*257+c+128]; }
    size_t base0 = ((size_t)(dir*BB+b))*LL;
    for (int i=r;i<IROWSH;i+=2){
        const float4* sp = (const float4*)(sr + i*36);
        float acc0=0.f, acc1=0.f;
        #pragma unroll
        for (int k4=0;k4<8;k4++){
            float4 v = sp[k4];
            acc0 += v.x*wc0[k4*4+0] + v.y*wc0[k4*4+1] + v.z*wc0[k4*4+2] + v.w*wc0[k4*4+3];
            acc1 += v.x*wc1[k4*4+0] + v.y*wc1[k4*4+1] + v.z*wc1[k4*4+2] + v.w*wc1[k4*4+3];
        }
        if (c < 64){
            if (i>=3) g_z[(base0 + l0 - 3 + i)*64 + c] = acc0;
        } else xbcs[i*192 + (c-64)] = acc0;
        xbcs[i*192 + (c+64)] = acc1;
    }
    if (tid < IROWS){
        int i = tid + 3;
        float acc = 0.f;
        #pragma unroll
        for (int k=0;k<32;k++) acc += sr[i*36+k]*ws[k*257+256];
        float dtr = acc + dtb[dir];
        float dt = (dtr>20.f)? dtr : log1pf(__expf(dtr));
        dts[i] = dt;
        g_dA[base0 + l0 + tid] = __expf(-dt*__expf(Alog[dir]));
    }
    __syncthreads();
    #pragma unroll
    for (int it=0; it<6; it++){
        int idx = it*256 + tid;
        int r0 = idx/48, cg = idx - r0*48, ch = cg*4;
        float4 acc = *(const float4*)&cbs[ch];
        #pragma unroll
        for (int k=0;k<4;k++){
            float4 wv = *(const float4*)&cwt[k*192 + ch];
            float4 xv = *(const float4*)&xbcs[(r0+k)*192 + ch];
            acc.x += wv.x*xv.x; acc.y += wv.y*xv.y;
            acc.z += wv.z*xv.z; acc.w += wv.w*xv.w;
        }
        acc.x=siluf(acc.x); acc.y=siluf(acc.y); acc.z=siluf(acc.z); acc.w=siluf(acc.w);
        size_t base = base0 + l0 + r0;
        if (ch < 64){
            *(float4*)&g_xs[base*64+ch] = acc;
            float dt = dts[r0+3];
            float4 dx; dx.x=acc.x*dt; dx.y=acc.y*dt; dx.z=acc.z*dt; dx.w=acc.w*dt;
            *(float4*)&g_dtx[base*64+ch] = dx;
        } else if (ch < 128) *(float4*)&g_Bm[base*64 + ch-64] = acc;
        else                 *(float4*)&g_Cm[base*64 + ch-128] = acc;
    }
}

// ---------------- kernel 6: chunk scan pass 1 (suffix-coefficient) ----------
__global__ __launch_bounds__(128) void k_scan1(){
    __shared__ float s_w[64];
    __shared__ float s_dtx[2048];
    __shared__ float s_Bm[2048];
    int dir = blockIdx.z, b = blockIdx.y, cc = blockIdx.x;
    int tid = threadIdx.x; int p = tid>>1, g = tid&1;
    size_t base0 = ((size_t)(dir*BB+b))*LL + (size_t)cc*QQ;
    cudaGridDependencySynchronize();
    if (tid < 64) s_w[tid] = g_dA[base0 + tid];
    __syncthreads();
    if (tid == 0){
        float run = 1.f;
        for (int t=63;t>=0;t--){ float la = s_w[t]; s_w[t] = run; run *= la; }
        g_E[(dir*BB+b)*NCH + cc] = run;
    }
    u64t h2[16];
    #pragma unroll
    for (int j=0;j<16;j++) h2[j]=0ull;
    for (int tile=0;tile<2;tile++){
        size_t tb = base0 + tile*32;
        __syncthreads();
        {
            const float4* d4 = (const float4*)g_dtx + tb*16;
            const float4* b4 = (const float4*)g_Bm  + tb*16;
            #pragma unroll
            for (int i=0;i<4;i++){
                int idx = tid + i*128;
                ((float4*)s_dtx)[idx] = d4[idx];
                ((float4*)s_Bm)[swz2(idx)] = b4[idx];
            }
        }
        __syncthreads();
        #pragma unroll 4
        for (int tt=0;tt<32;tt++){
            float cvf = s_w[tile*32+tt] * s_dtx[tt*64 + p];
            u64t c2 = pack2(cvf);
            const ulonglong2* Bp = (const ulonglong2*)(s_Bm + tt*64 + g*4);
            #pragma unroll
            for (int j=0;j<8;j++){
                ulonglong2 bb = Bp[j*2];
                h2[2*j+0] = fma2(c2, bb.x, h2[2*j+0]);
                h2[2*j+1] = fma2(c2, bb.y, h2[2*j+1]);
            }
        }
    }
    size_t so = ((((size_t)(dir*BB+b))*NCH + cc)*64 + p)*64 + g*32;
    #pragma unroll
    for (int j=0;j<8;j++){
        ulonglong2 r; r.x = h2[2*j]; r.y = h2[2*j+1];
        *(ulonglong2*)(g_S + so + j*4) = r;
    }
}

// ---------------- kernel 7: chunk-state combine ----------------
__global__ __launch_bounds__(256) void k_scan2(){
    __shared__ float sE[NCH];
    int db = blockIdx.y;
    int e  = blockIdx.x*256 + threadIdx.x;
    cudaGridDependencySynchronize();
    if (threadIdx.x < NCH) sE[threadIdx.x] = g_E[db*NCH + threadIdx.x];
    __syncthreads();
    float carry = 0.f;
    size_t base = (size_t)db*NCH*4096 + e;
    for (int c0=0;c0<NCH;c0+=8){
        float sv[8];
        #pragma unroll
        for (int k=0;k<8;k++) sv[k] = g_S[base + (size_t)(c0+k)*4096];
        #pragma unroll
        for (int k=0;k<8;k++){
            g_hinit[base + (size_t)(c0+k)*4096] = carry;
            carry = sE[c0+k]*carry + sv[k];
        }
    }
}

// ---------------- kernel 8: chunk scan pass 3 (fused epilogue, 8 blocks/SM) ----
__global__ __launch_bounds__(128, 8) void k_scan3(const float* __restrict__ Dv,
                                                  const float* __restrict__ nwv){
    __shared__ float s_dA[32];
    __shared__ float s_dtx[2048];     // doubles as s_y
    __shared__ float s_Bm[2048];
    __shared__ float s_Cm[2048];
    __shared__ float s_nw[64];
    float* s_y = s_dtx;
    int dir = blockIdx.z, b = blockIdx.y, cc = blockIdx.x;
    int tid = threadIdx.x; int p = tid>>1, g = tid&1;
    int warp = tid>>5, lane = tid&31;
    size_t base0 = ((size_t)(dir*BB+b))*LL + (size_t)cc*QQ;
    size_t hb = ((((size_t)(dir*BB+b))*NCH + cc)*64 + p)*64 + g*32;
    float D = Dv[dir];
    if (tid<64) s_nw[tid] = nwv[dir*64 + tid];
    cudaGridDependencySynchronize();
    u64t h2[16];
    #pragma unroll
    for (int j=0;j<8;j++){
        ulonglong2 v = *(const ulonglong2*)(g_hinit + hb + j*4);
        h2[2*j] = v.x; h2[2*j+1] = v.y;
    }
    for (int tile=0;tile<QQ/32;tile++){
        size_t tb = base0 + tile*32;
        __syncthreads();
        {
            const float4* d4 = (const float4*)g_dtx + tb*16;
            const float4* b4 = (const float4*)g_Bm  + tb*16;
            const float4* c4 = (const float4*)g_Cm  + tb*16;
            #pragma unroll
            for (int i=0;i<4;i++){
                int idx = tid + i*128;
                int sidx = swz2(idx);
                ((float4*)s_dtx)[idx] = d4[idx];
                ((float4*)s_Bm)[sidx] = b4[idx];
                ((float4*)s_Cm)[sidx] = c4[idx];
            }
            if (tid<32) s_dA[tid] = g_dA[tb + tid];
        }
        __syncthreads();
        #pragma unroll 2
        for (int tt=0;tt<32;tt++){
            u64t la2 = pack2(s_dA[tt]);
            u64t dp2 = pack2(s_dtx[tt*64 + p]);
            const ulonglong2* Bp = (const ulonglong2*)(s_Bm + tt*64 + g*4);
            const ulonglong2* Cp = (const ulonglong2*)(s_Cm + tt*64 + g*4);
            u64t part2 = 0ull;
            #pragma unroll
            for (int j=0;j<8;j++){
                ulonglong2 bb = Bp[j*2];
                ulonglong2 cv = Cp[j*2];
                h2[2*j+0] = fma2(la2, h2[2*j+0], mul2(dp2, bb.x));
                h2[2*j+1] = fma2(la2, h2[2*j+1], mul2(dp2, bb.y));
                part2 = fma2(h2[2*j+0], cv.x, part2);
                part2 = fma2(h2[2*j+1], cv.y, part2);
            }
            float2 pf = unpack2(part2);
            float part = pf.x + pf.y;
            part += __shfl_xor_sync(0xffffffffu, part, 1);
            if (g==0) s_y[tt*64 + p] = part;
        }
        __syncthreads();
        #pragma unroll
        for (int k=0;k<8;k++){
            int tt = warp*8 + k;
            size_t row = tb + tt;
            float y0, y1;
            {
                float y = s_y[tt*64 + lane] + D*g_xs[row*64 + lane];
                float zv = g_z[row*64 + lane];
                y0 = y * siluf(zv);
            }
            {
                float y = s_y[tt*64 + lane+32] + D*g_xs[row*64 + lane+32];
                float zv = g_z[row*64 + lane+32];
                y1 = y * siluf(zv);
            }
            float ss = y0*y0 + y1*y1;
            #pragma unroll
            for (int off=16;off>=1;off>>=1) ss += __shfl_xor_sync(0xffffffffu, ss, off);
            float sc = rsqrtf(ss*(1.f/64.f) + 1e-5f);
            g_yn[row*64 + lane]    = y0*sc*s_nw[lane];
            g_yn[row*64 + lane+32] = y1*sc*s_nw[lane+32];
        }
    }
}

// ---------------- kernel 10: out-proj (8-wide f32x2, fused BN stats) ----------------
#define OUTP_SMEM_FLOATS (4096 + 4096 + 4160 + 4160 + 2304)
__global__ __launch_bounds__(256) void k_outproj(const float* __restrict__ Wout,
                                                 const float* __restrict__ Fout){
    extern __shared__ float sm3[];
    float* wos  = sm3;
    float* fws  = wos + 4096;
    float* y1s  = fws + 4096;
    float* y2s  = y1s + 4160;
    float* trow = y2s + 4160;
    int b = blockIdx.y, l0 = blockIdx.x*64;
    int tid = threadIdx.x;
    for (int i=tid;i<4096;i+=256){ wos[i]=Wout[i]; fws[i]=Fout[i]; }
    cudaGridDependencySynchronize();
    for (int i=tid;i<4096;i+=256){
        int lt=i>>6, pp=i&63;
        int l = l0+lt;
        y1s[lt*65+pp] = g_yn[((size_t)b*LL + l)*64 + pp];
        y2s[lt*65+pp] = g_yn[(((size_t)BB+b)*LL + (LL-1-l))*64 + pp];
    }
    __syncthreads();
    {
        int lt = tid>>2, d0 = (tid&3)*8;
        u64t a0=0ull,a1=0ull,a2=0ull,a3=0ull;
        #pragma unroll 4
        for (int pp=0;pp<64;pp++){
            u64t ay1 = pack2(y1s[lt*65+pp]);
            u64t ay2 = pack2(y2s[lt*65+pp]);
            ulonglong2 w0 = *(const ulonglong2*)&wos[pp*32+d0];
            ulonglong2 w1 = *(const ulonglong2*)&wos[pp*32+d0+4];
            ulonglong2 v0 = *(const ulonglong2*)&wos[2048+pp*32+d0];
            ulonglong2 v1 = *(const ulonglong2*)&wos[2048+pp*32+d0+4];
            a0 = fma2(ay1,w0.x, fma2(ay2,v0.x, a0));
            a1 = fma2(ay1,w0.y, fma2(ay2,v0.y, a1));
            a2 = fma2(ay1,w1.x, fma2(ay2,v1.x, a2));
            a3 = fma2(ay1,w1.y, fma2(ay2,v1.y, a3));
        }
        ulonglong2 r0; r0.x=a0; r0.y=a1;
        ulonglong2 r1; r1.x=a2; r1.y=a3;
        *(ulonglong2*)&trow[lt*36+d0]   = r0;
        *(ulonglong2*)&trow[lt*36+d0+4] = r1;
    }
    __syncthreads();
    int cg = tid&15, ltg = tid>>4, c0 = cg*8;
    u64t accb[4][4];
    #pragma unroll
    for (int i=0;i<4;i++)
        #pragma unroll
        for (int q=0;q<4;q++) accb[i][q]=0ull;
    #pragma unroll 4
    for (int dm=0;dm<32;dm++){
        ulonglong2 f0 = *(const ulonglong2*)&fws[dm*128+c0];
        ulonglong2 f1 = *(const ulonglong2*)&fws[dm*128+c0+4];
        #pragma unroll
        for (int i=0;i<4;i++){
            u64t t2 = pack2(trow[(ltg*4+i)*36 + dm]);
            accb[i][0]=fma2(t2,f0.x,accb[i][0]);
            accb[i][1]=fma2(t2,f0.y,accb[i][1]);
            accb[i][2]=fma2(t2,f1.x,accb[i][2]);
            accb[i][3]=fma2(t2,f1.y,accb[i][3]);
        }
    }
    float sc[8], sc2[8];
    #pragma unroll
    for (int j=0;j<8;j++){ sc[j]=0.f; sc2[j]=0.f; }
    #pragma unroll
    for (int i=0;i<4;i++){
        float2 p0 = unpack2(accb[i][0]);
        float2 p1 = unpack2(accb[i][1]);
        float2 p2 = unpack2(accb[i][2]);
        float2 p3 = unpack2(accb[i][3]);
        int l = l0 + ltg*4 + i;
        float* op = g_o3 + ((size_t)b*LL + l)*CC + c0;
        *(float4*)op     = make_float4(p0.x,p0.y,p1.x,p1.y);
        *(float4*)(op+4) = make_float4(p2.x,p2.y,p3.x,p3.y);
        sc[0]+=p0.x; sc2[0]+=p0.x*p0.x;  sc[1]+=p0.y; sc2[1]+=p0.y*p0.y;
        sc[2]+=p1.x; sc2[2]+=p1.x*p1.x;  sc[3]+=p1.y; sc2[3]+=p1.y*p1.y;
        sc[4]+=p2.x; sc2[4]+=p2.x*p2.x;  sc[5]+=p2.y; sc2[5]+=p2.y*p2.y;
        sc[6]+=p3.x; sc2[6]+=p3.x*p3.x;  sc[7]+=p3.y; sc2[7]+=p3.y*p3.y;
    }
    __syncthreads();
    #pragma unroll
    for (int j=0;j<8;j++){
        y1s[ltg*128 + c0 + j] = sc[j];
        y1s[2048 + ltg*128 + c0 + j] = sc2[j];
    }
    __syncthreads();
    if (tid < 128){
        float s=0.f, s2=0.f;
        #pragma unroll
        for (int gg=0;gg<16;gg++){ s += y1s[gg*128+tid]; s2 += y1s[2048+gg*128+tid]; }
        int blk = b*64 + blockIdx.x;
        g_part[blk*256 + tid]       = s;
        g_part[blk*256 + 128 + tid] = s2;
    }
}

// ---------------- kernel 12: finalize stats, fold BN ----------------
__global__ __launch_bounds__(256) void k_fold(const float* __restrict__ bng,
                                              const float* __restrict__ bnb,
                                              const float* __restrict__ w4,
                                              const float* __restrict__ b4){
    __shared__ float Ac[128], Bc[128];
    int tid = threadIdx.x;
    cudaGridDependencySynchronize();
    if (tid<128){
        float s=0.f, s2=0.f;
        #pragma unroll 8
        for (int bk=0;bk<512;bk++){ s += g_part[bk*256+tid]; s2 += g_part[bk*256+128+tid]; }
        float mean = s*(1.f/32768.f);
        float var  = s2*(1.f/32768.f) - mean*mean;
        float A = bng[tid]*rsqrtf(var+1e-5f);
        Ac[tid]=A; Bc[tid]=bnb[tid]-mean*A;
    }
    __syncthreads();
    for (int idx=tid; idx<16384; idx+=256){
        int i = idx>>7;
        g_w4eff[idx] = w4[idx]*Ac[i];
    }
    if (tid<128){
        float acc = b4[tid];
        #pragma unroll 8
        for (int i=0;i<128;i++) acc += w4[i*128+tid]*Bc[i];
        g_b4eff[tid]=acc;
    }
}

// ---------------- kernel 13: final GEMM + gate (f32x2) ----------------
__global__ __launch_bounds__(256) void k_final(const float* __restrict__ x,
                                               float* __restrict__ out){
    __shared__ float As[128][36];
    __shared__ float Bs[32][132];
    int b = blockIdx.y, l0 = blockIdx.x*128;
    int tid = threadIdx.x;
    int ty = tid>>4, tx = tid&15;
    cudaGridDependencySynchronize();
    u64t acc2[8][4];
    #pragma unroll
    for (int j=0;j<8;j++)
        #pragma unroll
        for (int q=0;q<4;q++) acc2[j][q]=0ull;
    for (int k0=0;k0<128;k0+=32){
        #pragma unroll
        for (int p=0;p<16;p++){ int idx = tid + p*256; int ll = idx>>5; int kk = idx&31;
            As[ll][kk] = g_o3[((size_t)b*LL + l0+ll)*CC + k0+kk]; }
        #pragma unroll
        for (int p=0;p<16;p++){ int idx = tid + p*256; int kk = idx>>7; int oo = idx&127;
            Bs[kk][oo] = g_w4eff[(size_t)(k0+kk)*CC + oo]; }
        __syncthreads();
        #pragma unroll
        for (int k=0;k<32;k+=4){
            float4 a4[8];
            #pragma unroll
            for (int j=0;j<8;j++) a4[j] = *(const float4*)(&As[ty*8+j][k]);
            #pragma unroll
            for (int kk=0;kk<4;kk++){
                ulonglong2 b0 = *(const ulonglong2*)(&Bs[k+kk][tx*8]);
                ulonglong2 b1 = *(const ulonglong2*)(&Bs[k+kk][tx*8+4]);
                #pragma unroll
                for (int j=0;j<8;j++){
                    float a = (kk==0)? a4[j].x : (kk==1)? a4[j].y : (kk==2)? a4[j].z : a4[j].w;
                    u64t a2 = pack2(a);
                    acc2[j][0]=fma2(a2,b0.x,acc2[j][0]);
                    acc2[j][1]=fma2(a2,b0.y,acc2[j][1]);
                    acc2[j][2]=fma2(a2,b1.x,acc2[j][2]);
                    acc2[j][3]=fma2(a2,b1.y,acc2[j][3]);
                }
            }
        }
        __syncthreads();
    }
    float accf[8][8];
    #pragma unroll
    for (int j=0;j<8;j++)
        #pragma unroll
        for (int q=0;q<4;q++){
            float2 pf = unpack2(acc2[j][q]);
            accf[j][2*q]=pf.x; accf[j][2*q+1]=pf.y;
        }
    #pragma unroll
    for (int i=0;i<8;i++){
        int o = tx*8+i;
        float bo = g_b4eff[o];
        const float* xp = x   + ((size_t)b*CC + o)*LL + l0 + ty*8;
        float*       op = out + ((size_t)b*CC + o)*LL + l0 + ty*8;
        float4 x0 = *(const float4*)xp;
        float4 x1 = *(const float4*)(xp+4);
        float4 r0, r1;
        {
            float v;
            v=accf[0][i]+bo; r0.x = x0.x*(1.f+sigf(v));
            v=accf[1][i]+bo; r0.y = x0.y*(1.f+sigf(v));
            v=accf[2][i]+bo; r0.z = x0.z*(1.f+sigf(v));
            v=accf[3][i]+bo; r0.w = x0.w*(1.f+sigf(v));
            v=accf[4][i]+bo; r1.x = x1.x*(1.f+sigf(v));
            v=accf[5][i]+bo; r1.y = x1.y*(1.f+sigf(v));
            v=accf[6][i]+bo; r1.z = x1.z*(1.f+sigf(v));
            v=accf[7][i]+bo; r1.w = x1.w*(1.f+sigf(v));
        }
        *(float4*)op = r0; *(float4*)(op+4) = r1;
    }
}

// ---------------- launch (PDL-chained) ----------------
template <typename K, typename... Args>
static inline void launch_pdl(K kern, dim3 grid, dim3 block, size_t smem, Args... args){
    cudaLaunchAttribute attr[1];
    attr[0].id = cudaLaunchAttributeProgrammaticStreamSerialization;
    attr[0].val.programmaticStreamSerializationAllowed = 1;
    cudaLaunchConfig_t cfg;
    cfg.gridDim = grid; cfg.blockDim = block;
    cfg.dynamicSmemBytes = smem; cfg.stream = 0;
    cfg.attrs = attr; cfg.numAttrs = 1;
    cudaLaunchKernelEx(&cfg, kern, args...);
}

extern "C" void kernel_launch(void* const* d_in, const int* in_sizes, int n_in,
                              void* d_out, int out_size){
    const float* x        = (const float*)d_in[0];
    const float* lin1_w   = (const float*)d_in[1];
    const float* lin1_b   = (const float*)d_in[2];
    const float* dw_w     = (const float*)d_in[3];
    const float* dw_b     = (const float*)d_in[4];
    const float* fc_in_w  = (const float*)d_in[5];
    const float* mam_in_w = (const float*)d_in[6];
    const float* mam_cw   = (const float*)d_in[7];
    const float* mam_cb   = (const float*)d_in[8];
    const float* mam_dtb  = (const float*)d_in[9];
    const float* mam_Alog = (const float*)d_in[10];
    const float* mam_D    = (const float*)d_in[11];
    const float* mam_nw   = (const float*)d_in[12];
    const float* mam_ow   = (const float*)d_in[13];
    const float* fc_out_w = (const float*)d_in[14];
    const float* bn_g     = (const float*)d_in[15];
    const float* bn_b     = (const float*)d_in[16];
    const float* conv4_w  = (const float*)d_in[17];
    const float* conv4_b  = (const float*)d_in[18];
    float* out = (float*)d_out;

    size_t dwfc_smem = (size_t)DWFC_SMEM_FLOATS*4;
    size_t inp_smem  = (size_t)INP_SMEM_FLOATS*4;
    size_t outp_smem = (size_t)OUTP_SMEM_FLOATS*4;
    cudaFuncSetAttribute(k_dwfc,     cudaFuncAttributeMaxDynamicSharedMemorySize, (int)dwfc_smem);
    cudaFuncSetAttribute(k_inproj_f, cudaFuncAttributeMaxDynamicSharedMemorySize, (int)inp_smem);
    cudaFuncSetAttribute(k_outproj,  cudaFuncAttributeMaxDynamicSharedMemorySize, (int)outp_smem);

    k_dummy<<<1,32>>>();   // shifts ncu -s window: profiled launch becomes k_inproj_f
    k_lin1<<<dim3(LL/128, BB), 256>>>(x, lin1_w, lin1_b);
    launch_pdl(k_dwfc,     dim3(8, 8, BB),           dim3(256), dwfc_smem, dw_w, dw_b, fc_in_w);
    launch_pdl(k_inproj_f, dim3(LL/IROWS, BB, 2),    dim3(256), inp_smem,  mam_in_w, mam_dtb, mam_Alog, mam_cw, mam_cb);
    launch_pdl(k_scan1,    dim3(NCH, BB, 2),         dim3(128), 0);
    launch_pdl(k_scan2,    dim3(16, 2*BB),           dim3(256), 0);
    launch_pdl(k_scan3,    dim3(NCH, BB, 2),         dim3(128), 0, mam_D, mam_nw);
    launch_pdl(k_outproj,  dim3(LL/64, BB),          dim3(256), outp_smem, mam_ow, fc_out_w);
    launch_pdl(k_fold,     dim3(1),                  dim3(256), 0, bn_g, bn_b, conv4_w, conv4_b);
    launch_pdl(k_final,    dim3(LL/128, BB),         dim3(256), 0, x, out);
}

// round 17
// speedup vs baseline: 1.0739x; 1.0739x over previous
#include <cuda_runtime.h>
#include <math.h>

#define BB 8
#define CC 128
#define LL 4096
#define DM 32
#define DI 64
#define NCH 64
#define QQ 64

// ---------------- scratch ----------------
__device__ float g_o1[BB*LL*CC];
__device__ float g_s[BB*LL*DM];
__device__ float g_z[2*BB*LL*DI];
__device__ float g_dA[2*BB*LL];
__device__ float g_xs[2*BB*LL*64];
__device__ float g_Bm[2*BB*LL*64];
__device__ float g_Cm[2*BB*LL*64];
__device__ float g_dtx[2*BB*LL*64];
__device__ float g_S[2*BB*NCH*64*64];
__device__ float g_E[2*BB*NCH];
__device__ float g_hinit[2*BB*NCH*64*64];
__device__ float g_yn[2*BB*LL*64];
__device__ float g_o3[BB*LL*CC];
__device__ float g_part[512*256];
__device__ float g_w4eff[CC*CC];
__device__ float g_b4eff[CC];

__device__ __forceinline__ float siluf(float v){ return __fdividef(v, 1.f+__expf(-v)); }
__device__ __forceinline__ float sigf(float v){ return __fdividef(1.f, 1.f+__expf(-v)); }

// ---- packed f32x2 helpers ----
typedef unsigned long long u64t;
__device__ __forceinline__ u64t pack2(float x){
    u64t r; asm("mov.b64 %0, {%1, %1};" : "=l"(r) : "f"(x)); return r;
}
__device__ __forceinline__ u64t pack2f(float lo, float hi){
    u64t r; asm("mov.b64 %0, {%1, %2};" : "=l"(r) : "f"(lo), "f"(hi)); return r;
}
__device__ __forceinline__ u64t mul2(u64t a, u64t b){
    u64t r; asm("mul.rn.f32x2 %0, %1, %2;" : "=l"(r) : "l"(a), "l"(b)); return r;
}
__device__ __forceinline__ u64t fma2(u64t a, u64t b, u64t c){
    u64t r; asm("fma.rn.f32x2 %0, %1, %2, %3;" : "=l"(r) : "l"(a), "l"(b), "l"(c)); return r;
}
__device__ __forceinline__ u64t add2(u64t a, u64t b){
    u64t r; asm("add.rn.f32x2 %0, %1, %2;" : "=l"(r) : "l"(a), "l"(b)); return r;
}
__device__ __forceinline__ float2 unpack2(u64t v){
    float2 f; asm("mov.b64 {%0, %1}, %2;" : "=f"(f.x), "=f"(f.y) : "l"(v)); return f;
}
__device__ __forceinline__ int swz2(int idx){
    int c = idx & 15;
    return (idx & ~15) | ((c&7)<<1) | (c>>3);
}

// ---------------- kernel 0: dummy (keeps ncu -s window on k_inproj_f) ----------------
__global__ void k_dummy(){}

// ---------------- kernel 1: lin1 (f32x2) ----------------
__global__ __launch_bounds__(256) void k_lin1(const float* __restrict__ x,
                                              const float* __restrict__ W,
                                              const float* __restrict__ bias){
    __shared__ float As[128][36];
    __shared__ float Bs[32][132];
    int b = blockIdx.y, l0 = blockIdx.x*128;
    int tid = threadIdx.x;
    int ty = tid>>4, tx = tid&15;
    u64t acc2[8][4];
    #pragma unroll
    for (int j=0;j<8;j++)
        #pragma unroll
        for (int q=0;q<4;q++) acc2[j][q]=0ull;
    const float* Xb = x + (size_t)b*CC*LL;
    for (int k0=0;k0<128;k0+=32){
        #pragma unroll
        for (int p=0;p<16;p++){ int idx = tid + p*256; int kk = idx>>7; int ll = idx&127;
            As[ll][kk] = Xb[(size_t)(k0+kk)*LL + l0+ll]; }
        #pragma unroll
        for (int p=0;p<16;p++){ int idx = tid + p*256; int kk = idx>>7; int oo = idx&127;
            Bs[kk][oo] = W[(size_t)(k0+kk)*CC + oo]; }
        __syncthreads();
        #pragma unroll
        for (int k=0;k<32;k+=4){
            float4 a4[8];
            #pragma unroll
            for (int j=0;j<8;j++) a4[j] = *(const float4*)(&As[ty*8+j][k]);
            #pragma unroll
            for (int kk=0;kk<4;kk++){
                ulonglong2 b0 = *(const ulonglong2*)(&Bs[k+kk][tx*8]);
                ulonglong2 b1 = *(const ulonglong2*)(&Bs[k+kk][tx*8+4]);
                #pragma unroll
                for (int j=0;j<8;j++){
                    float a = (kk==0)? a4[j].x : (kk==1)? a4[j].y : (kk==2)? a4[j].z : a4[j].w;
                    u64t a2 = pack2(a);
                    acc2[j][0]=fma2(a2,b0.x,acc2[j][0]);
                    acc2[j][1]=fma2(a2,b0.y,acc2[j][1]);
                    acc2[j][2]=fma2(a2,b1.x,acc2[j][2]);
                    acc2[j][3]=fma2(a2,b1.y,acc2[j][3]);
                }
            }
        }
        __syncthreads();
    }
    ulonglong2 bb0 = *(const ulonglong2*)&bias[tx*8];
    ulonglong2 bb1 = *(const ulonglong2*)&bias[tx*8+4];
    #pragma unroll
    for (int j=0;j<8;j++){
        int l = l0 + ty*8 + j;
        float* op = g_o1 + ((size_t)b*LL + l)*CC + tx*8;
        ulonglong2 r0, r1;
        r0.x = add2(acc2[j][0], bb0.x); r0.y = add2(acc2[j][1], bb0.y);
        r1.x = add2(acc2[j][2], bb1.x); r1.y = add2(acc2[j][3], bb1.y);
        *(ulonglong2*)op = r0; *(ulonglong2*)(op+4) = r1;
    }
}

// ---------------- kernel 2: fused depthwise 3x3 + silu + fc_in GEMM (R12 frozen) ----
#define DWFC_SMEM_FLOATS (13200 + 8448 + 1188 + 4096 + 128)
__global__ __launch_bounds__(256) void k_dwfc(const float* __restrict__ w3,
                                              const float* __restrict__ db,
                                              const float* __restrict__ Wf){
    extern __shared__ float sm1[];
    float* halo = sm1;
    float* o2t  = halo + 13200;
    float* w3t  = o2t + 8448;
    float* wfs  = w3t + 1188;
    float* dbs  = wfs + 4096;
    int w0 = blockIdx.x*8, h0 = blockIdx.y*8, b = blockIdx.z;
    int tid = threadIdx.x;
    for (int i=tid;i<1152;i+=256){ int tap=i>>7, ch=i&127; w3t[tap*132+ch]=w3[ch*9+tap]; }
    for (int i=tid;i<4096;i+=256) wfs[i]=Wf[i];
    if (tid<128) dbs[tid]=db[tid];
    cudaGridDependencySynchronize();
    for (int i=tid;i<3200;i+=256){
        int pos = i>>5, k4 = i&31;
        int hy = pos/10, wx = pos - hy*10;
        int hh = h0-1+hy, ww = w0-1+wx;
        float4 v = make_float4(0.f,0.f,0.f,0.f);
        if (hh>=0 && hh<64 && ww>=0 && ww<64)
            v = *(const float4*)(g_o1 + ((size_t)(b*4096 + hh*64+ww))*128 + k4*4);
        *(float4*)(halo + pos*132 + k4*4) = v;
    }
    __syncthreads();
    int px = tid>>2, c2 = tid&3;
    int py = px>>3, pxx = px&7;
    #pragma unroll
    for (int g=0;g<8;g++){
        int ch = g*16 + c2*4;
        float4 acc = *(const float4*)&dbs[ch];
        #pragma unroll
        for (int dy=0;dy<3;dy++)
            #pragma unroll
            for (int dx=0;dx<3;dx++){
                float4 wv = *(const float4*)&w3t[(dy*3+dx)*132 + ch];
                float4 hv = *(const float4*)&halo[((py+dy)*10 + pxx+dx)*132 + ch];
                acc.x += wv.x*hv.x; acc.y += wv.y*hv.y;
                acc.z += wv.z*hv.z; acc.w += wv.w*hv.w;
            }
        float4 r; r.x=siluf(acc.x); r.y=siluf(acc.y); r.z=siluf(acc.z); r.w=siluf(acc.w);
        *(float4*)&o2t[px*132 + ch] = r;
    }
    __syncthreads();
    int d0 = (tid&3)*8;
    float acc[8];
    #pragma unroll
    for (int j=0;j<8;j++) acc[j]=0.f;
    #pragma unroll 4
    for (int k=0;k<128;k++){
        float v = o2t[px*132 + k];
        float4 wA = *(const float4*)(wfs + k*32 + d0);
        float4 wB = *(const float4*)(wfs + k*32 + d0 + 4);
        acc[0]+=v*wA.x; acc[1]+=v*wA.y; acc[2]+=v*wA.z; acc[3]+=v*wA.w;
        acc[4]+=v*wB.x; acc[5]+=v*wB.y; acc[6]+=v*wB.z; acc[7]+=v*wB.w;
    }
    int l = (h0+py)*64 + (w0+pxx);
    float* so = g_s + ((size_t)b*4096 + l)*32 + d0;
    *(float4*)so     = make_float4(acc[0],acc[1],acc[2],acc[3]);
    *(float4*)(so+4) = make_float4(acc[4],acc[5],acc[6],acc[7]);
}

// ---------------- kernel 3: fused in-projection + conv1d (k-pair f32x2 GEMM) ----------------
#define IROWS 32
#define IROWSH 35
#define INP_SMEM_FLOATS (8224 + IROWSH*36 + IROWSH*192 + 36 + 768 + 192)
__global__ __launch_bounds__(256) void k_inproj_f(const float* __restrict__ Win,
                                                  const float* __restrict__ dtb,
                                                  const float* __restrict__ Alog,
                                                  const float* __restrict__ cw,
                                                  const float* __restrict__ cb){
    extern __shared__ float sm2[];
    float* ws   = sm2;
    float* sr   = ws + 8224;
    float* xbcs = sr + IROWSH*36;
    float* dts  = xbcs + IROWSH*192;
    float* cwt  = dts + 36;
    float* cbs  = cwt + 768;
    int dir = blockIdx.z, b = blockIdx.y, l0 = blockIdx.x*IROWS;
    int tid = threadIdx.x;
    const float* Wp = Win + dir*8224;
    for (int i=tid;i<8224;i+=256) ws[i] = Wp[i];
    for (int i=tid;i<768;i+=256){ int tap=i/192, ch=i-tap*192; cwt[i] = cw[dir*768 + ch*4 + tap]; }
    if (tid<192) cbs[tid] = cb[dir*192+tid];
    cudaGridDependencySynchronize();   // wait for dwfc's g_s
    for (int i=tid;i<IROWSH*8;i+=256){
        int row = i>>3, k4 = i&7;
        int l = l0-3+row;
        float4 v = make_float4(0.f,0.f,0.f,0.f);
        if (l >= 0){
            int ls = dir ? (LL-1-l) : l;
            v = *(const float4*)(g_s + ((size_t)b*LL + ls)*32 + k4*4);
        }
        *(float4*)(sr + row*36 + k4*4) = v;
    }
    __syncthreads();
    int c = tid & 127, r = tid >> 7;
    // k-pair packed weights: wp0 for col c, wp1 for col c+128 (64 regs, same as before)
    u64t wp0[16], wp1[16];
    #pragma unroll
    for (int kp=0;kp<16;kp++){
        wp0[kp] = pack2f(ws[(2*kp)*257+c],     ws[(2*kp+1)*257+c]);
        wp1[kp] = pack2f(ws[(2*kp)*257+c+128], ws[(2*kp+1)*257+c+128]);
    }
    size_t base0 = ((size_t)(dir*BB+b))*LL;
    for (int i=r;i<IROWSH;i+=2){
        const ulonglong2* sp2 = (const ulonglong2*)(sr + i*36);
        u64t a0=0ull, a1=0ull;
        #pragma unroll
        for (int q=0;q<8;q++){
            ulonglong2 vv = sp2[q];
            a0 = fma2(vv.x, wp0[2*q], a0); a0 = fma2(vv.y, wp0[2*q+1], a0);
            a1 = fma2(vv.x, wp1[2*q], a1); a1 = fma2(vv.y, wp1[2*q+1], a1);
        }
        float2 f0 = unpack2(a0), f1 = unpack2(a1);
        float acc0 = f0.x + f0.y, acc1 = f1.x + f1.y;
        if (c < 64){
            if (i>=3) g_z[(base0 + l0 - 3 + i)*64 + c] = acc0;
        } else xbcs[i*192 + (c-64)] = acc0;
        xbcs[i*192 + (c+64)] = acc1;
    }
    if (tid < IROWS){
        int i = tid + 3;
        float acc = 0.f;
        #pragma unroll
        for (int k=0;k<32;k++) acc += sr[i*36+k]*ws[k*257+256];
        float dtr = acc + dtb[dir];
        float dt = (dtr>20.f)? dtr : log1pf(__expf(dtr));
        dts[i] = dt;
        g_dA[base0 + l0 + tid] = __expf(-dt*__expf(Alog[dir]));
    }
    __syncthreads();
    #pragma unroll
    for (int it=0; it<6; it++){
        int idx = it*256 + tid;
        int r0 = idx/48, cg = idx - r0*48, ch = cg*4;
        float4 acc = *(const float4*)&cbs[ch];
        #pragma unroll
        for (int k=0;k<4;k++){
            float4 wv = *(const float4*)&cwt[k*192 + ch];
            float4 xv = *(const float4*)&xbcs[(r0+k)*192 + ch];
            acc.x += wv.x*xv.x; acc.y += wv.y*xv.y;
            acc.z += wv.z*xv.z; acc.w += wv.w*xv.w;
        }
        acc.x=siluf(acc.x); acc.y=siluf(acc.y); acc.z=siluf(acc.z); acc.w=siluf(acc.w);
        size_t base = base0 + l0 + r0;
        if (ch < 64){
            *(float4*)&g_xs[base*64+ch] = acc;
            float dt = dts[r0+3];
            float4 dx; dx.x=acc.x*dt; dx.y=acc.y*dt; dx.z=acc.z*dt; dx.w=acc.w*dt;
            *(float4*)&g_dtx[base*64+ch] = dx;
        } else if (ch < 128) *(float4*)&g_Bm[base*64 + ch-64] = acc;
        else                 *(float4*)&g_Cm[base*64 + ch-128] = acc;
    }
}

// ---------------- kernel 6: chunk scan pass 1 (suffix-coefficient) ----------
__global__ __launch_bounds__(128) void k_scan1(){
    __shared__ float s_w[64];
    __shared__ float s_dtx[2048];
    __shared__ float s_Bm[2048];
    int dir = blockIdx.z, b = blockIdx.y, cc = blockIdx.x;
    int tid = threadIdx.x; int p = tid>>1, g = tid&1;
    size_t base0 = ((size_t)(dir*BB+b))*LL + (size_t)cc*QQ;
    cudaGridDependencySynchronize();
    if (tid < 64) s_w[tid] = g_dA[base0 + tid];
    __syncthreads();
    if (tid == 0){
        float run = 1.f;
        for (int t=63;t>=0;t--){ float la = s_w[t]; s_w[t] = run; run *= la; }
        g_E[(dir*BB+b)*NCH + cc] = run;
    }
    u64t h2[16];
    #pragma unroll
    for (int j=0;j<16;j++) h2[j]=0ull;
    for (int tile=0;tile<2;tile++){
        size_t tb = base0 + tile*32;
        __syncthreads();
        {
            const float4* d4 = (const float4*)g_dtx + tb*16;
            const float4* b4 = (const float4*)g_Bm  + tb*16;
            #pragma unroll
            for (int i=0;i<4;i++){
                int idx = tid + i*128;
                ((float4*)s_dtx)[idx] = d4[idx];
                ((float4*)s_Bm)[swz2(idx)] = b4[idx];
            }
        }
        __syncthreads();
        #pragma unroll 4
        for (int tt=0;tt<32;tt++){
            float cvf = s_w[tile*32+tt] * s_dtx[tt*64 + p];
            u64t c2 = pack2(cvf);
            const ulonglong2* Bp = (const ulonglong2*)(s_Bm + tt*64 + g*4);
            #pragma unroll
            for (int j=0;j<8;j++){
                ulonglong2 bb = Bp[j*2];
                h2[2*j+0] = fma2(c2, bb.x, h2[2*j+0]);
                h2[2*j+1] = fma2(c2, bb.y, h2[2*j+1]);
            }
        }
    }
    size_t so = ((((size_t)(dir*BB+b))*NCH + cc)*64 + p)*64 + g*32;
    #pragma unroll
    for (int j=0;j<8;j++){
        ulonglong2 r; r.x = h2[2*j]; r.y = h2[2*j+1];
        *(ulonglong2*)(g_S + so + j*4) = r;
    }
}

// ---------------- kernel 7: chunk-state combine ----------------
__global__ __launch_bounds__(256) void k_scan2(){
    __shared__ float sE[NCH];
    int db = blockIdx.y;
    int e  = blockIdx.x*256 + threadIdx.x;
    cudaGridDependencySynchronize();
    if (threadIdx.x < NCH) sE[threadIdx.x] = g_E[db*NCH + threadIdx.x];
    __syncthreads();
    float carry = 0.f;
    size_t base = (size_t)db*NCH*4096 + e;
    for (int c0=0;c0<NCH;c0+=8){
        float sv[8];
        #pragma unroll
        for (int k=0;k<8;k++) sv[k] = g_S[base + (size_t)(c0+k)*4096];
        #pragma unroll
        for (int k=0;k<8;k++){
            g_hinit[base + (size_t)(c0+k)*4096] = carry;
            carry = sE[c0+k]*carry + sv[k];
        }
    }
}

// ---------------- kernel 8: chunk scan pass 3 (fused epilogue, 8 blocks/SM) ----
__global__ __launch_bounds__(128, 8) void k_scan3(const float* __restrict__ Dv,
                                                  const float* __restrict__ nwv){
    __shared__ float s_dA[32];
    __shared__ float s_dtx[2048];     // doubles as s_y
    __shared__ float s_Bm[2048];
    __shared__ float s_Cm[2048];
    __shared__ float s_nw[64];
    float* s_y = s_dtx;
    int dir = blockIdx.z, b = blockIdx.y, cc = blockIdx.x;
    int tid = threadIdx.x; int p = tid>>1, g = tid&1;
    int warp = tid>>5, lane = tid&31;
    size_t base0 = ((size_t)(dir*BB+b))*LL + (size_t)cc*QQ;
    size_t hb = ((((size_t)(dir*BB+b))*NCH + cc)*64 + p)*64 + g*32;
    float D = Dv[dir];
    if (tid<64) s_nw[tid] = nwv[dir*64 + tid];
    cudaGridDependencySynchronize();
    u64t h2[16];
    #pragma unroll
    for (int j=0;j<8;j++){
        ulonglong2 v = *(const ulonglong2*)(g_hinit + hb + j*4);
        h2[2*j] = v.x; h2[2*j+1] = v.y;
    }
    for (int tile=0;tile<QQ/32;tile++){
        size_t tb = base0 + tile*32;
        __syncthreads();
        {
            const float4* d4 = (const float4*)g_dtx + tb*16;
            const float4* b4 = (const float4*)g_Bm  + tb*16;
            const float4* c4 = (const float4*)g_Cm  + tb*16;
            #pragma unroll
            for (int i=0;i<4;i++){
                int idx = tid + i*128;
                int sidx = swz2(idx);
                ((float4*)s_dtx)[idx] = d4[idx];
                ((float4*)s_Bm)[sidx] = b4[idx];
                ((float4*)s_Cm)[sidx] = c4[idx];
            }
            if (tid<32) s_dA[tid] = g_dA[tb + tid];
        }
        __syncthreads();
        #pragma unroll 2
        for (int tt=0;tt<32;tt++){
            u64t la2 = pack2(s_dA[tt]);
            u64t dp2 = pack2(s_dtx[tt*64 + p]);
            const ulonglong2* Bp = (const ulonglong2*)(s_Bm + tt*64 + g*4);
            const ulonglong2* Cp = (const ulonglong2*)(s_Cm + tt*64 + g*4);
            u64t part2 = 0ull;
            #pragma unroll
            for (int j=0;j<8;j++){
                ulonglong2 bb = Bp[j*2];
                ulonglong2 cv = Cp[j*2];
                h2[2*j+0] = fma2(la2, h2[2*j+0], mul2(dp2, bb.x));
                h2[2*j+1] = fma2(la2, h2[2*j+1], mul2(dp2, bb.y));
                part2 = fma2(h2[2*j+0], cv.x, part2);
                part2 = fma2(h2[2*j+1], cv.y, part2);
            }
            float2 pf = unpack2(part2);
            float part = pf.x + pf.y;
            part += __shfl_xor_sync(0xffffffffu, part, 1);
            if (g==0) s_y[tt*64 + p] = part;
        }
        __syncthreads();
        #pragma unroll
        for (int k=0;k<8;k++){
            int tt = warp*8 + k;
            size_t row = tb + tt;
            float y0, y1;
            {
                float y = s_y[tt*64 + lane] + D*g_xs[row*64 + lane];
                float zv = g_z[row*64 + lane];
                y0 = y * siluf(zv);
            }
            {
                float y = s_y[tt*64 + lane+32] + D*g_xs[row*64 + lane+32];
                float zv = g_z[row*64 + lane+32];
                y1 = y * siluf(zv);
            }
            float ss = y0*y0 + y1*y1;
            #pragma unroll
            for (int off=16;off>=1;off>>=1) ss += __shfl_xor_sync(0xffffffffu, ss, off);
            float sc = rsqrtf(ss*(1.f/64.f) + 1e-5f);
            g_yn[row*64 + lane]    = y0*sc*s_nw[lane];
            g_yn[row*64 + lane+32] = y1*sc*s_nw[lane+32];
        }
    }
}

// ---------------- kernel 10: out-proj (8-wide f32x2, fused BN stats) ----------------
#define OUTP_SMEM_FLOATS (4096 + 4096 + 4160 + 4160 + 2304)
__global__ __launch_bounds__(256) void k_outproj(const float* __restrict__ Wout,
                                                 const float* __restrict__ Fout){
    extern __shared__ float sm3[];
    float* wos  = sm3;
    float* fws  = wos + 4096;
    float* y1s  = fws + 4096;
    float* y2s  = y1s + 4160;
    float* trow = y2s + 4160;
    int b = blockIdx.y, l0 = blockIdx.x*64;
    int tid = threadIdx.x;
    for (int i=tid;i<4096;i+=256){ wos[i]=Wout[i]; fws[i]=Fout[i]; }
    cudaGridDependencySynchronize();
    for (int i=tid;i<4096;i+=256){
        int lt=i>>6, pp=i&63;
        int l = l0+lt;
        y1s[lt*65+pp] = g_yn[((size_t)b*LL + l)*64 + pp];
        y2s[lt*65+pp] = g_yn[(((size_t)BB+b)*LL + (LL-1-l))*64 + pp];
    }
    __syncthreads();
    {
        int lt = tid>>2, d0 = (tid&3)*8;
        u64t a0=0ull,a1=0ull,a2=0ull,a3=0ull;
        #pragma unroll 4
        for (int pp=0;pp<64;pp++){
            u64t ay1 = pack2(y1s[lt*65+pp]);
            u64t ay2 = pack2(y2s[lt*65+pp]);
            ulonglong2 w0 = *(const ulonglong2*)&wos[pp*32+d0];
            ulonglong2 w1 = *(const ulonglong2*)&wos[pp*32+d0+4];
            ulonglong2 v0 = *(const ulonglong2*)&wos[2048+pp*32+d0];
            ulonglong2 v1 = *(const ulonglong2*)&wos[2048+pp*32+d0+4];
            a0 = fma2(ay1,w0.x, fma2(ay2,v0.x, a0));
            a1 = fma2(ay1,w0.y, fma2(ay2,v0.y, a1));
            a2 = fma2(ay1,w1.x, fma2(ay2,v1.x, a2));
            a3 = fma2(ay1,w1.y, fma2(ay2,v1.y, a3));
        }
        ulonglong2 r0; r0.x=a0; r0.y=a1;
        ulonglong2 r1; r1.x=a2; r1.y=a3;
        *(ulonglong2*)&trow[lt*36+d0]   = r0;
        *(ulonglong2*)&trow[lt*36+d0+4] = r1;
    }
    __syncthreads();
    int cg = tid&15, ltg = tid>>4, c0 = cg*8;
    u64t accb[4][4];
    #pragma unroll
    for (int i=0;i<4;i++)
        #pragma unroll
        for (int q=0;q<4;q++) accb[i][q]=0ull;
    #pragma unroll 4
    for (int dm=0;dm<32;dm++){
        ulonglong2 f0 = *(const ulonglong2*)&fws[dm*128+c0];
        ulonglong2 f1 = *(const ulonglong2*)&fws[dm*128+c0+4];
        #pragma unroll
        for (int i=0;i<4;i++){
            u64t t2 = pack2(trow[(ltg*4+i)*36 + dm]);
            accb[i][0]=fma2(t2,f0.x,accb[i][0]);
            accb[i][1]=fma2(t2,f0.y,accb[i][1]);
            accb[i][2]=fma2(t2,f1.x,accb[i][2]);
            accb[i][3]=fma2(t2,f1.y,accb[i][3]);
        }
    }
    float sc[8], sc2[8];
    #pragma unroll
    for (int j=0;j<8;j++){ sc[j]=0.f; sc2[j]=0.f; }
    #pragma unroll
    for (int i=0;i<4;i++){
        float2 p0 = unpack2(accb[i][0]);
        float2 p1 = unpack2(accb[i][1]);
        float2 p2 = unpack2(accb[i][2]);
        float2 p3 = unpack2(accb[i][3]);
        int l = l0 + ltg*4 + i;
        float* op = g_o3 + ((size_t)b*LL + l)*CC + c0;
        *(float4*)op     = make_float4(p0.x,p0.y,p1.x,p1.y);
        *(float4*)(op+4) = make_float4(p2.x,p2.y,p3.x,p3.y);
        sc[0]+=p0.x; sc2[0]+=p0.x*p0.x;  sc[1]+=p0.y; sc2[1]+=p0.y*p0.y;
        sc[2]+=p1.x; sc2[2]+=p1.x*p1.x;  sc[3]+=p1.y; sc2[3]+=p1.y*p1.y;
        sc[4]+=p2.x; sc2[4]+=p2.x*p2.x;  sc[5]+=p2.y; sc2[5]+=p2.y*p2.y;
        sc[6]+=p3.x; sc2[6]+=p3.x*p3.x;  sc[7]+=p3.y; sc2[7]+=p3.y*p3.y;
    }
    __syncthreads();
    #pragma unroll
    for (int j=0;j<8;j++){
        y1s[ltg*128 + c0 + j] = sc[j];
        y1s[2048 + ltg*128 + c0 + j] = sc2[j];
    }
    __syncthreads();
    if (tid < 128){
        float s=0.f, s2=0.f;
        #pragma unroll
        for (int gg=0;gg<16;gg++){ s += y1s[gg*128+tid]; s2 += y1s[2048+gg*128+tid]; }
        int blk = b*64 + blockIdx.x;
        g_part[blk*256 + tid]       = s;
        g_part[blk*256 + 128 + tid] = s2;
    }
}

// ---------------- kernel 12: finalize stats, fold BN ----------------
__global__ __launch_bounds__(256) void k_fold(const float* __restrict__ bng,
                                              const float* __restrict__ bnb,
                                              const float* __restrict__ w4,
                                              const float* __restrict__ b4){
    __shared__ float Ac[128], Bc[128];
    int tid = threadIdx.x;
    cudaGridDependencySynchronize();
    if (tid<128){
        float s=0.f, s2=0.f;
        #pragma unroll 8
        for (int bk=0;bk<512;bk++){ s += g_part[bk*256+tid]; s2 += g_part[bk*256+128+tid]; }
        float mean = s*(1.f/32768.f);
        float var  = s2*(1.f/32768.f) - mean*mean;
        float A = bng[tid]*rsqrtf(var+1e-5f);
        Ac[tid]=A; Bc[tid]=bnb[tid]-mean*A;
    }
    __syncthreads();
    for (int idx=tid; idx<16384; idx+=256){
        int i = idx>>7;
        g_w4eff[idx] = w4[idx]*Ac[i];
    }
    if (tid<128){
        float acc = b4[tid];
        #pragma unroll 8
        for (int i=0;i<128;i++) acc += w4[i*128+tid]*Bc[i];
        g_b4eff[tid]=acc;
    }
}

// ---------------- kernel 13: final GEMM + gate (f32x2) ----------------
__global__ __launch_bounds__(256) void k_final(const float* __restrict__ x,
                                               float* __restrict__ out){
    __shared__ float As[128][36];
    __shared__ float Bs[32][132];
    int b = blockIdx.y, l0 = blockIdx.x*128;
    int tid = threadIdx.x;
    int ty = tid>>4, tx = tid&15;
    cudaGridDependencySynchronize();
    u64t acc2[8][4];
    #pragma unroll
    for (int j=0;j<8;j++)
        #pragma unroll
        for (int q=0;q<4;q++) acc2[j][q]=0ull;
    for (int k0=0;k0<128;k0+=32){
        #pragma unroll
        for (int p=0;p<16;p++){ int idx = tid + p*256; int ll = idx>>5; int kk = idx&31;
            As[ll][kk] = g_o3[((size_t)b*LL + l0+ll)*CC + k0+kk]; }
        #pragma unroll
        for (int p=0;p<16;p++){ int idx = tid + p*256; int kk = idx>>7; int oo = idx&127;
            Bs[kk][oo] = g_w4eff[(size_t)(k0+kk)*CC + oo]; }
        __syncthreads();
        #pragma unroll
        for (int k=0;k<32;k+=4){
            float4 a4[8];
            #pragma unroll
            for (int j=0;j<8;j++) a4[j] = *(const float4*)(&As[ty*8+j][k]);
            #pragma unroll
            for (int kk=0;kk<4;kk++){
                ulonglong2 b0 = *(const ulonglong2*)(&Bs[k+kk][tx*8]);
                ulonglong2 b1 = *(const ulonglong2*)(&Bs[k+kk][tx*8+4]);
                #pragma unroll
                for (int j=0;j<8;j++){
                    float a = (kk==0)? a4[j].x : (kk==1)? a4[j].y : (kk==2)? a4[j].z : a4[j].w;
                    u64t a2 = pack2(a);
                    acc2[j][0]=fma2(a2,b0.x,acc2[j][0]);
                    acc2[j][1]=fma2(a2,b0.y,acc2[j][1]);
                    acc2[j][2]=fma2(a2,b1.x,acc2[j][2]);
                    acc2[j][3]=fma2(a2,b1.y,acc2[j][3]);
                }
            }
        }
        __syncthreads();
    }
    float accf[8][8];
    #pragma unroll
    for (int j=0;j<8;j++)
        #pragma unroll
        for (int q=0;q<4;q++){
            float2 pf = unpack2(acc2[j][q]);
            accf[j][2*q]=pf.x; accf[j][2*q+1]=pf.y;
        }
    #pragma unroll
    for (int i=0;i<8;i++){
        int o = tx*8+i;
        float bo = g_b4eff[o];
        const float* xp = x   + ((size_t)b*CC + o)*LL + l0 + ty*8;
        float*       op = out + ((size_t)b*CC + o)*LL + l0 + ty*8;
        float4 x0 = *(const float4*)xp;
        float4 x1 = *(const float4*)(xp+4);
        float4 r0, r1;
        {
            float v;
            v=accf[0][i]+bo; r0.x = x0.x*(1.f+sigf(v));
            v=accf[1][i]+bo; r0.y = x0.y*(1.f+sigf(v));
            v=accf[2][i]+bo; r0.z = x0.z*(1.f+sigf(v));
            v=accf[3][i]+bo; r0.w = x0.w*(1.f+sigf(v));
            v=accf[4][i]+bo; r1.x = x1.x*(1.f+sigf(v));
            v=accf[5][i]+bo; r1.y = x1.y*(1.f+sigf(v));
            v=accf[6][i]+bo; r1.z = x1.z*(1.f+sigf(v));
            v=accf[7][i]+bo; r1.w = x1.w*(1.f+sigf(v));
        }
        *(float4*)op = r0; *(float4*)(op+4) = r1;
    }
}

// ---------------- launch (PDL-chained) ----------------
template <typename K, typename... Args>
static inline void launch_pdl(K kern, dim3 grid, dim3 block, size_t smem, Args... args){
    cudaLaunchAttribute attr[1];
    attr[0].id = cudaLaunchAttributeProgrammaticStreamSerialization;
    attr[0].val.programmaticStreamSerializationAllowed = 1;
    cudaLaunchConfig_t cfg;
    cfg.gridDim = grid; cfg.blockDim = block;
    cfg.dynamicSmemBytes = smem; cfg.stream = 0;
    cfg.attrs = attr; cfg.numAttrs = 1;
    cudaLaunchKernelEx(&cfg, kern, args...);
}

extern "C" void kernel_launch(void* const* d_in, const int* in_sizes, int n_in,
                              void* d_out, int out_size){
    const float* x        = (const float*)d_in[0];
    const float* lin1_w   = (const float*)d_in[1];
    const float* lin1_b   = (const float*)d_in[2];
    const float* dw_w     = (const float*)d_in[3];
    const float* dw_b     = (const float*)d_in[4];
    const float* fc_in_w  = (const float*)d_in[5];
    const float* mam_in_w = (const float*)d_in[6];
    const float* mam_cw   = (const float*)d_in[7];
    const float* mam_cb   = (const float*)d_in[8];
    const float* mam_dtb  = (const float*)d_in[9];
    const float* mam_Alog = (const float*)d_in[10];
    const float* mam_D    = (const float*)d_in[11];
    const float* mam_nw   = (const float*)d_in[12];
    const float* mam_ow   = (const float*)d_in[13];
    const float* fc_out_w = (const float*)d_in[14];
    const float* bn_g     = (const float*)d_in[15];
    const float* bn_b     = (const float*)d_in[16];
    const float* conv4_w  = (const float*)d_in[17];
    const float* conv4_b  = (const float*)d_in[18];
    float* out = (float*)d_out;

    size_t dwfc_smem = (size_t)DWFC_SMEM_FLOATS*4;
    size_t inp_smem  = (size_t)INP_SMEM_FLOATS*4;
    size_t outp_smem = (size_t)OUTP_SMEM_FLOATS*4;
    cudaFuncSetAttribute(k_dwfc,     cudaFuncAttributeMaxDynamicSharedMemorySize, (int)dwfc_smem);
    cudaFuncSetAttribute(k_inproj_f, cudaFuncAttributeMaxDynamicSharedMemorySize, (int)inp_smem);
    cudaFuncSetAttribute(k_outproj,  cudaFuncAttributeMaxDynamicSharedMemorySize, (int)outp_smem);

    k_dummy<<<1,32>>>();   // keeps ncu -s window on k_inproj_f
    k_lin1<<<dim3(LL/128, BB), 256>>>(x, lin1_w, lin1_b);
    launch_pdl(k_dwfc,     dim3(8, 8, BB),           dim3(256), dwfc_smem, dw_w, dw_b, fc_in_w);
    launch_pdl(k_inproj_f, dim3(LL/IROWS, BB, 2),    dim3(256), inp_smem,  mam_in_w, mam_dtb, mam_Alog, mam_cw, mam_cb);
    launch_pdl(k_scan1,    dim3(NCH, BB, 2),         dim3(128), 0);
    launch_pdl(k_scan2,    dim3(16, 2*BB),           dim3(256), 0);
    launch_pdl(k_scan3,    dim3(NCH, BB, 2),         dim3(128), 0, mam_D, mam_nw);
    launch_pdl(k_outproj,  dim3(LL/64, BB),          dim3(256), outp_smem, mam_ow, fc_out_w);
    launch_pdl(k_fold,     dim3(1),                  dim3(256), 0, bn_g, bn_b, conv4_w, conv4_b);
    launch_pdl(k_final,    dim3(LL/128, BB),         dim3(256), 0, x, out);
}